// round 7
// baseline (speedup 1.0000x reference)
#include <cuda_runtime.h>
#include <math.h>

#define NND 100000
#define NE  1600000
#define D   128

typedef unsigned long long u64;

// Scratch (static device globals — no runtime allocation allowed)
__device__ float g_buf [NND * D];   // layer-1 messages
__device__ float g2_buf[NND * D];   // layer-2 messages
__device__ float dis_buf[NND];
__device__ int   deg_buf[NND];
__device__ int   scan_tmp[NND];
__device__ int   row_ptr[NND + 1];
__device__ int   cursor[NND];
__device__ int   csr_src[NE];
__device__ int   bsum[256];
__device__ float Wf_buf[D * 64];    // fused head weight  Wp1@Wp2
__device__ float bF_buf[64];        // fused head bias    bp1@Wp2 + bp2

// ---------------- f32x2 helpers ----------------

__device__ __forceinline__ u64 ffma2(u64 a, u64 b, u64 c) {
    u64 d;
    asm("fma.rn.f32x2 %0, %1, %2, %3;" : "=l"(d) : "l"(a), "l"(b), "l"(c));
    return d;
}
__device__ __forceinline__ u64 pack_dup(float x) {
    u64 r;
    asm("mov.b64 %0, {%1, %1};" : "=l"(r) : "f"(x));
    return r;
}
__device__ __forceinline__ float2 unpack2(u64 v) {
    float2 r;
    asm("mov.b64 {%0, %1}, %2;" : "=f"(r.x), "=f"(r.y) : "l"(v));
    return r;
}

// ---------------- degree / normalization / CSR build ----------------

__global__ void k_init_deg() {
    int i = blockIdx.x * blockDim.x + threadIdx.x;
    if (i < NND) deg_buf[i] = 0;
}

__global__ void k_count_deg(const int* __restrict__ dst) {
    int e = blockIdx.x * blockDim.x + threadIdx.x;
    if (e < NE) atomicAdd(&deg_buf[dst[e]], 1);
}

__global__ void k_dis() {
    int i = blockIdx.x * blockDim.x + threadIdx.x;
    if (i < NND) dis_buf[i] = rsqrtf((float)(deg_buf[i] + 1));
}

#define SCB 512
#define SCAN_BLOCKS ((NND + SCB - 1) / SCB)   // 196

__global__ __launch_bounds__(SCB) void k_scan1() {
    __shared__ int sm[SCB];
    int i = blockIdx.x * SCB + threadIdx.x;
    int v = (i < NND) ? deg_buf[i] : 0;
    sm[threadIdx.x] = v;
    __syncthreads();
#pragma unroll
    for (int off = 1; off < SCB; off <<= 1) {
        int t = (threadIdx.x >= off) ? sm[threadIdx.x - off] : 0;
        __syncthreads();
        sm[threadIdx.x] += t;
        __syncthreads();
    }
    if (i < NND) scan_tmp[i] = sm[threadIdx.x];
    if (threadIdx.x == SCB - 1) bsum[blockIdx.x] = sm[SCB - 1];
}

__global__ __launch_bounds__(256) void k_scan2() {
    __shared__ int sm[256];
    int v = (threadIdx.x < SCAN_BLOCKS) ? bsum[threadIdx.x] : 0;
    sm[threadIdx.x] = v;
    __syncthreads();
#pragma unroll
    for (int off = 1; off < 256; off <<= 1) {
        int t = (threadIdx.x >= off) ? sm[threadIdx.x - off] : 0;
        __syncthreads();
        sm[threadIdx.x] += t;
        __syncthreads();
    }
    bsum[threadIdx.x] = sm[threadIdx.x];  // inclusive
}

__global__ __launch_bounds__(SCB) void k_scan3() {
    int i = blockIdx.x * SCB + threadIdx.x;
    if (i >= NND) return;
    int off = (blockIdx.x > 0) ? bsum[blockIdx.x - 1] : 0;
    int inc = scan_tmp[i] + off;
    int st  = inc - deg_buf[i];
    row_ptr[i] = st;
    cursor[i]  = st;
    if (i == NND - 1) row_ptr[NND] = inc;
}

__global__ void k_fill(const int* __restrict__ src, const int* __restrict__ dst) {
    int e = blockIdx.x * blockDim.x + threadIdx.x;
    if (e >= NE) return;
    int p = atomicAdd(&cursor[dst[e]], 1);
    csr_src[p] = src[e];
}

// ---------------- fused head weight precompute ----------------

__global__ __launch_bounds__(256) void k_fusew(const float* __restrict__ Wp1,
                                               const float* __restrict__ bp1,
                                               const float* __restrict__ Wp2,
                                               const float* __restrict__ bp2)
{
    int i = blockIdx.x * blockDim.x + threadIdx.x;
    if (i >= D * 64) return;
    int k = i >> 6, n = i & 63;
    float s = 0.0f;
#pragma unroll 8
    for (int j = 0; j < D; j++)
        s = fmaf(Wp1[k * D + j], Wp2[j * 64 + n], s);
    Wf_buf[i] = s;
    if (k == 0) {
        float t = bp2[n];
#pragma unroll 8
        for (int j = 0; j < D; j++)
            t = fmaf(bp1[j], Wp2[j * 64 + n], t);
        bF_buf[n] = t;
    }
}

// ---------------- GEMM1: C = A[M,128] @ W[128,128] (plain) ----------------

__global__ __launch_bounds__(256, 2)
void gemm1(const float* __restrict__ A, const float* __restrict__ W,
           float* __restrict__ C, int M)
{
    constexpr int BM = 128, K = 128, KC = 32, TM = 8, BN = 128, TP = 4;
    constexpr int SAP = KC + 4;
    __shared__ float As[BM * SAP];
    __shared__ u64   Ws2[KC * BN / 2];

    const int tid  = threadIdx.x;
    const int row0 = blockIdx.x * BM;
    const int tx   = tid & 15;
    const int ty   = tid >> 4;

    u64 acc[TM][TP];
#pragma unroll
    for (int i = 0; i < TM; i++)
#pragma unroll
        for (int j = 0; j < TP; j++) acc[i][j] = 0ULL;

    for (int kc = 0; kc < K; kc += KC) {
#pragma unroll
        for (int p = 0; p < (BM * KC / 4) / 256; p++) {
            int i  = tid + p * 256;
            int r  = i / (KC / 4);
            int c4 = i % (KC / 4);
            float4 v = make_float4(0.f, 0.f, 0.f, 0.f);
            int row = row0 + r;
            if (row < M)
                v = *(const float4*)(A + row * K + kc + c4 * 4);
            *(float4*)(As + r * SAP + c4 * 4) = v;
        }
#pragma unroll
        for (int p = 0; p < (KC * BN / 4) / 256; p++) {
            int i = tid + p * 256;
            ((float4*)Ws2)[i] = *(const float4*)(W + kc * BN + i * 4);
        }
        __syncthreads();

#pragma unroll 8
        for (int k = 0; k < KC; k++) {
            u64 wp[TP];
#pragma unroll
            for (int j = 0; j < TP; j++)
                wp[j] = Ws2[k * (BN / 2) + j * 16 + tx];
            float a[TM];
#pragma unroll
            for (int i = 0; i < TM; i++)
                a[i] = As[(ty * TM + i) * SAP + k];
            u64 ap[TM];
#pragma unroll
            for (int i = 0; i < TM; i++) ap[i] = pack_dup(a[i]);
#pragma unroll
            for (int i = 0; i < TM; i++)
#pragma unroll
                for (int j = 0; j < TP; j++)
                    acc[i][j] = ffma2(ap[i], wp[j], acc[i][j]);
        }
        __syncthreads();
    }

#pragma unroll
    for (int i = 0; i < TM; i++) {
        int row = row0 + ty * TM + i;
        if (row >= M) break;
#pragma unroll
        for (int j = 0; j < TP; j++) {
            float2 v = unpack2(acc[i][j]);
            *(float2*)(C + row * BN + 2 * (tx + j * 16)) = v;
        }
    }
}

// ---------------- FUSED: gather+finalize (into smem) then GEMM on same rows ----------
// Phase 1 (per block, 8 warps, warp-per-node over 128 rows):
//   a = [dis-weighted] CSR-sum of g rows + self term; As[row] = relu(dis[v]*a + biasA)
// Phase 2: GEMM  C = As @ W  with epilogue:
//   EPI 0: C = acc * dis[row]                       (layer-2 messages, BN=128)
//   EPI 2: C = log_softmax(acc + biasC) over row    (head, BN=64)

template <int BN, int TN, bool SCALE_MSG, int EPI>
__global__ __launch_bounds__(256, 2)
void k_fused(const float* __restrict__ g,
             const float* __restrict__ W,
             const float* __restrict__ biasA,
             const float* __restrict__ biasC,
             const float* __restrict__ dis,
             float* __restrict__ C)
{
    constexpr int BM = 128, K = 128, KC = 32, TM = 8;
    constexpr int TP  = TN / 2;
    constexpr int SAP = K + 4;   // full-K A row stride in smem
    extern __shared__ __align__(16) char smem_raw[];
    float* As  = (float*)smem_raw;                       // BM*SAP floats
    u64*   Ws2 = (u64*)(smem_raw + BM * SAP * 4);        // KC*BN/2 u64

    const int tid  = threadIdx.x;
    const int wid  = tid >> 5;
    const int lane = tid & 31;
    const int row0 = blockIdx.x * BM;

    // ---- phase 1: gather + finalize into As ----
    {
        const float4* gp = (const float4*)g;
        float4 bb = ((const float4*)biasA)[lane];
        for (int n = wid; n < BM; n += 8) {
            int node = row0 + n;
            float4 r = make_float4(0.f, 0.f, 0.f, 0.f);
            if (node < NND) {
                int beg = row_ptr[node];
                int end = row_ptr[node + 1];
                float4 a = gp[node * 32 + lane];    // self-loop message
                float dv = dis[node];
                if (SCALE_MSG) { a.x *= dv; a.y *= dv; a.z *= dv; a.w *= dv; }
                int e = beg;
                for (; e + 4 <= end; e += 4) {
                    int s0 = __ldg(&csr_src[e + 0]);
                    int s1 = __ldg(&csr_src[e + 1]);
                    int s2 = __ldg(&csr_src[e + 2]);
                    int s3 = __ldg(&csr_src[e + 3]);
                    float4 v0 = gp[s0 * 32 + lane];
                    float4 v1 = gp[s1 * 32 + lane];
                    float4 v2 = gp[s2 * 32 + lane];
                    float4 v3 = gp[s3 * 32 + lane];
                    if (SCALE_MSG) {
                        float d0 = __ldg(&dis[s0]), d1 = __ldg(&dis[s1]);
                        float d2 = __ldg(&dis[s2]), d3 = __ldg(&dis[s3]);
                        a.x = fmaf(v0.x, d0, a.x); a.y = fmaf(v0.y, d0, a.y);
                        a.z = fmaf(v0.z, d0, a.z); a.w = fmaf(v0.w, d0, a.w);
                        a.x = fmaf(v1.x, d1, a.x); a.y = fmaf(v1.y, d1, a.y);
                        a.z = fmaf(v1.z, d1, a.z); a.w = fmaf(v1.w, d1, a.w);
                        a.x = fmaf(v2.x, d2, a.x); a.y = fmaf(v2.y, d2, a.y);
                        a.z = fmaf(v2.z, d2, a.z); a.w = fmaf(v2.w, d2, a.w);
                        a.x = fmaf(v3.x, d3, a.x); a.y = fmaf(v3.y, d3, a.y);
                        a.z = fmaf(v3.z, d3, a.z); a.w = fmaf(v3.w, d3, a.w);
                    } else {
                        a.x += v0.x + v1.x + v2.x + v3.x;
                        a.y += v0.y + v1.y + v2.y + v3.y;
                        a.z += v0.z + v1.z + v2.z + v3.z;
                        a.w += v0.w + v1.w + v2.w + v3.w;
                    }
                }
                for (; e < end; e++) {
                    int s = __ldg(&csr_src[e]);
                    float4 v = gp[s * 32 + lane];
                    if (SCALE_MSG) {
                        float ds = __ldg(&dis[s]);
                        a.x = fmaf(v.x, ds, a.x); a.y = fmaf(v.y, ds, a.y);
                        a.z = fmaf(v.z, ds, a.z); a.w = fmaf(v.w, ds, a.w);
                    } else {
                        a.x += v.x; a.y += v.y; a.z += v.z; a.w += v.w;
                    }
                }
                r.x = fmaxf(fmaf(a.x, dv, bb.x), 0.f);
                r.y = fmaxf(fmaf(a.y, dv, bb.y), 0.f);
                r.z = fmaxf(fmaf(a.z, dv, bb.z), 0.f);
                r.w = fmaxf(fmaf(a.w, dv, bb.w), 0.f);
            }
            *(float4*)(As + n * SAP + lane * 4) = r;
        }
    }
    __syncthreads();

    // ---- phase 2: GEMM  As[BM,128] @ W[128,BN] ----
    const int tx = tid & 15;
    const int ty = tid >> 4;

    u64 acc[TM][TP];
#pragma unroll
    for (int i = 0; i < TM; i++)
#pragma unroll
        for (int j = 0; j < TP; j++) acc[i][j] = 0ULL;

    for (int kc = 0; kc < K; kc += KC) {
#pragma unroll
        for (int p = 0; p < (KC * BN / 4) / 256; p++) {
            int i = tid + p * 256;
            ((float4*)Ws2)[i] = *(const float4*)(W + kc * BN + i * 4);
        }
        __syncthreads();

#pragma unroll 8
        for (int k = 0; k < KC; k++) {
            u64 wp[TP];
#pragma unroll
            for (int j = 0; j < TP; j++)
                wp[j] = Ws2[k * (BN / 2) + j * 16 + tx];
            float a[TM];
#pragma unroll
            for (int i = 0; i < TM; i++)
                a[i] = As[(ty * TM + i) * SAP + kc + k];
            u64 ap[TM];
#pragma unroll
            for (int i = 0; i < TM; i++) ap[i] = pack_dup(a[i]);
#pragma unroll
            for (int i = 0; i < TM; i++)
#pragma unroll
                for (int j = 0; j < TP; j++)
                    acc[i][j] = ffma2(ap[i], wp[j], acc[i][j]);
        }
        __syncthreads();
    }

    if (EPI == 0) {
#pragma unroll
        for (int i = 0; i < TM; i++) {
            int row = row0 + ty * TM + i;
            if (row >= NND) break;
            float s = dis[row];
#pragma unroll
            for (int j = 0; j < TP; j++) {
                float2 v = unpack2(acc[i][j]);
                v.x *= s; v.y *= s;
                *(float2*)(C + row * BN + 2 * (tx + j * 16)) = v;
            }
        }
    } else {  // EPI 2: BN=64, TP=2, full row across 16 lanes
        float2 b0 = *(const float2*)(biasC + 2 * tx);
        float2 b1 = *(const float2*)(biasC + 2 * (tx + 16));
#pragma unroll
        for (int i = 0; i < TM; i++) {
            int row = row0 + ty * TM + i;
            float2 v0 = unpack2(acc[i][0]);
            float2 v1 = unpack2(acc[i][1]);
            float t0 = v0.x + b0.x, t1 = v0.y + b0.y;
            float t2 = v1.x + b1.x, t3 = v1.y + b1.y;
            float m = fmaxf(fmaxf(t0, t1), fmaxf(t2, t3));
#pragma unroll
            for (int o = 8; o; o >>= 1) m = fmaxf(m, __shfl_xor_sync(0xFFFFFFFFu, m, o));
            float s = expf(t0 - m) + expf(t1 - m) + expf(t2 - m) + expf(t3 - m);
#pragma unroll
            for (int o = 8; o; o >>= 1) s += __shfl_xor_sync(0xFFFFFFFFu, s, o);
            float l = m + logf(s);
            if (row < NND) {
                float2 r0, r1;
                r0.x = t0 - l; r0.y = t1 - l;
                r1.x = t2 - l; r1.y = t3 - l;
                *(float2*)(C + row * BN + 2 * tx)        = r0;
                *(float2*)(C + row * BN + 2 * (tx + 16)) = r1;
            }
        }
    }
}

// ---------------- launch ----------------

extern "C" void kernel_launch(void* const* d_in, const int* in_sizes, int n_in,
                              void* d_out, int out_size)
{
    const float* x   = (const float*)d_in[0];
    const int*   ei  = (const int*)d_in[1];
    const int*   src = ei;
    const int*   dst = ei + NE;
    const float* W1  = (const float*)d_in[2];
    const float* b1  = (const float*)d_in[3];
    const float* W2  = (const float*)d_in[4];
    const float* b2  = (const float*)d_in[5];
    const float* Wp1 = (const float*)d_in[6];
    const float* bp1 = (const float*)d_in[7];
    const float* Wp2 = (const float*)d_in[8];
    const float* bp2 = (const float*)d_in[9];
    float* out = (float*)d_out;

    float *g_p, *g2_p, *dis_p, *wf_p, *bf_p;
    cudaGetSymbolAddress((void**)&g_p,   g_buf);
    cudaGetSymbolAddress((void**)&g2_p,  g2_buf);
    cudaGetSymbolAddress((void**)&dis_p, dis_buf);
    cudaGetSymbolAddress((void**)&wf_p,  Wf_buf);
    cudaGetSymbolAddress((void**)&bf_p,  bF_buf);

    // smem sizes for fused kernels
    constexpr int SAP = D + 4;
    const int SM1 = D * SAP * 4 + (32 * 128 / 2) * 8;   // 83968 B
    const int SM2 = D * SAP * 4 + (32 * 64 / 2) * 8;    // 75776 B

    // one-time setup (outside graph capture semantics: attribute set + stream/events)
    static cudaStream_t s2 = nullptr;
    static cudaEvent_t ev_fork, ev_csr;
    if (!s2) {
        cudaStreamCreateWithFlags(&s2, cudaStreamNonBlocking);
        cudaEventCreateWithFlags(&ev_fork, cudaEventDisableTiming);
        cudaEventCreateWithFlags(&ev_csr,  cudaEventDisableTiming);
        cudaFuncSetAttribute((const void*)k_fused<128, 8, true, 0>,
                             cudaFuncAttributeMaxDynamicSharedMemorySize, SM1);
        cudaFuncSetAttribute((const void*)k_fused<64, 4, false, 2>,
                             cudaFuncAttributeMaxDynamicSharedMemorySize, SM2);
    }

    const int GEMM_BLOCKS = (NND + 127) / 128;   // 782

    // ---- fork: CSR build + norm + head-weight fusion on s2, GEMM1 on main ----
    cudaEventRecord(ev_fork, 0);
    cudaStreamWaitEvent(s2, ev_fork, 0);

    k_fusew<<<(D * 64 + 255) / 256, 256, 0, s2>>>(Wp1, bp1, Wp2, bp2);
    k_init_deg<<<(NND + 255) / 256, 256, 0, s2>>>();
    k_count_deg<<<(NE + 255) / 256, 256, 0, s2>>>(dst);
    k_dis<<<(NND + 255) / 256, 256, 0, s2>>>();
    k_scan1<<<SCAN_BLOCKS, SCB, 0, s2>>>();
    k_scan2<<<1, 256, 0, s2>>>();
    k_scan3<<<SCAN_BLOCKS, SCB, 0, s2>>>();
    k_fill<<<(NE + 255) / 256, 256, 0, s2>>>(src, dst);
    cudaEventRecord(ev_csr, s2);

    // GEMM1 (main): g = x@W1 (plain, no dis dependency)
    gemm1<<<GEMM_BLOCKS, 256>>>(x, W1, g_p, NND);

    cudaStreamWaitEvent(0, ev_csr, 0);

    // ---- fused layer 2: [gather1 + finalize(b1)] -> GEMM(W2) -> g2 = .*dis ----
    k_fused<128, 8, true, 0><<<GEMM_BLOCKS, 256, SM1>>>(
        g_p, W2, b1, nullptr, dis_p, g2_p);

    // ---- fused head: [gather2 + finalize(b2)] -> GEMM(Wf) -> log_softmax -> out ----
    k_fused<64, 4, false, 2><<<GEMM_BLOCKS, 256, SM2>>>(
        g2_p, wf_p, b2, bf_p, dis_p, out);
}

// round 8
// speedup vs baseline: 1.2893x; 1.2893x over previous
#include <cuda_runtime.h>
#include <cuda_fp16.h>
#include <math.h>

#define NND 100000
#define NE  1600000
#define D   128

typedef unsigned long long u64;

// Scratch (static device globals — no runtime allocation allowed)
__device__ __half g_buf [NND * D];   // layer-1 messages (fp16)
__device__ __half g2_buf[NND * D];   // layer-2 messages (fp16)
__device__ float acc_buf[NND * D];   // finalized activations h (fp32)
__device__ float dis_buf[NND];
__device__ int   deg_buf[NND];
__device__ int   scan_tmp[NND];
__device__ int   row_ptr[NND + 1];
__device__ int   cursor[NND];
__device__ int   csr_src[NE];
__device__ int   bsum[256];
__device__ float Wf_buf[D * 64];     // fused head weight  Wp1@Wp2
__device__ float bF_buf[64];         // fused head bias    bp1@Wp2 + bp2

// ---------------- f32x2 helpers ----------------

__device__ __forceinline__ u64 ffma2(u64 a, u64 b, u64 c) {
    u64 d;
    asm("fma.rn.f32x2 %0, %1, %2, %3;" : "=l"(d) : "l"(a), "l"(b), "l"(c));
    return d;
}
__device__ __forceinline__ u64 pack_dup(float x) {
    u64 r;
    asm("mov.b64 %0, {%1, %1};" : "=l"(r) : "f"(x));
    return r;
}
__device__ __forceinline__ float2 unpack2(u64 v) {
    float2 r;
    asm("mov.b64 {%0, %1}, %2;" : "=f"(r.x), "=f"(r.y) : "l"(v));
    return r;
}

// ---------------- degree / normalization / CSR build ----------------

__global__ void k_init_deg() {
    int i = blockIdx.x * blockDim.x + threadIdx.x;
    if (i < NND) deg_buf[i] = 0;
}

__global__ void k_count_deg(const int* __restrict__ dst) {
    int e = blockIdx.x * blockDim.x + threadIdx.x;
    if (e < NE) atomicAdd(&deg_buf[dst[e]], 1);
}

__global__ void k_dis() {
    int i = blockIdx.x * blockDim.x + threadIdx.x;
    if (i < NND) dis_buf[i] = rsqrtf((float)(deg_buf[i] + 1));
}

#define SCB 512
#define SCAN_BLOCKS ((NND + SCB - 1) / SCB)   // 196

__global__ __launch_bounds__(SCB) void k_scan1() {
    __shared__ int sm[SCB];
    int i = blockIdx.x * SCB + threadIdx.x;
    int v = (i < NND) ? deg_buf[i] : 0;
    sm[threadIdx.x] = v;
    __syncthreads();
#pragma unroll
    for (int off = 1; off < SCB; off <<= 1) {
        int t = (threadIdx.x >= off) ? sm[threadIdx.x - off] : 0;
        __syncthreads();
        sm[threadIdx.x] += t;
        __syncthreads();
    }
    if (i < NND) scan_tmp[i] = sm[threadIdx.x];
    if (threadIdx.x == SCB - 1) bsum[blockIdx.x] = sm[SCB - 1];
}

__global__ __launch_bounds__(256) void k_scan2() {
    __shared__ int sm[256];
    int v = (threadIdx.x < SCAN_BLOCKS) ? bsum[threadIdx.x] : 0;
    sm[threadIdx.x] = v;
    __syncthreads();
#pragma unroll
    for (int off = 1; off < 256; off <<= 1) {
        int t = (threadIdx.x >= off) ? sm[threadIdx.x - off] : 0;
        __syncthreads();
        sm[threadIdx.x] += t;
        __syncthreads();
    }
    bsum[threadIdx.x] = sm[threadIdx.x];  // inclusive
}

__global__ __launch_bounds__(SCB) void k_scan3() {
    int i = blockIdx.x * SCB + threadIdx.x;
    if (i >= NND) return;
    int off = (blockIdx.x > 0) ? bsum[blockIdx.x - 1] : 0;
    int inc = scan_tmp[i] + off;
    int st  = inc - deg_buf[i];
    row_ptr[i] = st;
    cursor[i]  = st;
    if (i == NND - 1) row_ptr[NND] = inc;
}

__global__ void k_fill(const int* __restrict__ src, const int* __restrict__ dst) {
    int e = blockIdx.x * blockDim.x + threadIdx.x;
    if (e >= NE) return;
    int p = atomicAdd(&cursor[dst[e]], 1);
    csr_src[p] = src[e];
}

// ---------------- fused head weight precompute ----------------

__global__ __launch_bounds__(256) void k_fusew(const float* __restrict__ Wp1,
                                               const float* __restrict__ bp1,
                                               const float* __restrict__ Wp2,
                                               const float* __restrict__ bp2)
{
    int i = blockIdx.x * blockDim.x + threadIdx.x;
    if (i >= D * 64) return;
    int k = i >> 6, n = i & 63;
    float s = 0.0f;
#pragma unroll 8
    for (int j = 0; j < D; j++)
        s = fmaf(Wp1[k * D + j], Wp2[j * 64 + n], s);
    Wf_buf[i] = s;
    if (k == 0) {
        float t = bp2[n];
#pragma unroll 8
        for (int j = 0; j < D; j++)
            t = fmaf(bp1[j], Wp2[j * 64 + n], t);
        bF_buf[n] = t;
    }
}

// ---------------- GEMM: C[rows,BN] = A[rows,128] @ W[128,BN] + epilogue ----------------
// EPI 0: Chalf = half(acc * dis[row])          (message write, fp16)
// EPI 3: Chalf = half(acc)                     (message write, fp16, no scale)
// EPI 2: Cf = log_softmax(acc + biasC) (fp32)  (final output, BN=64)

template <int BN, int TN, int EPI>
__global__ __launch_bounds__(256, 2)
void gemm_k128(const float* __restrict__ A,
               const float* __restrict__ W,
               const float* __restrict__ biasC,
               const float* __restrict__ dis,
               __half* __restrict__ Chalf,
               float* __restrict__ Cf,
               int M)
{
    constexpr int BM = 128, K = 128, KC = 32, TM = 8;
    constexpr int TP  = TN / 2;
    constexpr int SAP = KC + 4;
    __shared__ float As[BM * SAP];
    __shared__ u64   Ws2[KC * BN / 2];

    const int tid  = threadIdx.x;
    const int row0 = blockIdx.x * BM;
    const int tx   = tid & 15;
    const int ty   = tid >> 4;

    u64 acc[TM][TP];
#pragma unroll
    for (int i = 0; i < TM; i++)
#pragma unroll
        for (int j = 0; j < TP; j++) acc[i][j] = 0ULL;

    for (int kc = 0; kc < K; kc += KC) {
#pragma unroll
        for (int p = 0; p < (BM * KC / 4) / 256; p++) {
            int i  = tid + p * 256;
            int r  = i / (KC / 4);
            int c4 = i % (KC / 4);
            float4 v = make_float4(0.f, 0.f, 0.f, 0.f);
            int row = row0 + r;
            if (row < M)
                v = *(const float4*)(A + row * K + kc + c4 * 4);
            *(float4*)(As + r * SAP + c4 * 4) = v;
        }
#pragma unroll
        for (int p = 0; p < (KC * BN / 4) / 256; p++) {
            int i = tid + p * 256;
            ((float4*)Ws2)[i] = *(const float4*)(W + kc * BN + i * 4);
        }
        __syncthreads();

#pragma unroll 8
        for (int k = 0; k < KC; k++) {
            u64 wp[TP];
#pragma unroll
            for (int j = 0; j < TP; j++)
                wp[j] = Ws2[k * (BN / 2) + j * 16 + tx];
            float a[TM];
#pragma unroll
            for (int i = 0; i < TM; i++)
                a[i] = As[(ty * TM + i) * SAP + k];
            u64 ap[TM];
#pragma unroll
            for (int i = 0; i < TM; i++) ap[i] = pack_dup(a[i]);
#pragma unroll
            for (int i = 0; i < TM; i++)
#pragma unroll
                for (int j = 0; j < TP; j++)
                    acc[i][j] = ffma2(ap[i], wp[j], acc[i][j]);
        }
        __syncthreads();
    }

    if (EPI == 0 || EPI == 3) {
#pragma unroll
        for (int i = 0; i < TM; i++) {
            int row = row0 + ty * TM + i;
            if (row >= M) break;
            float s = (EPI == 0) ? dis[row] : 1.0f;
#pragma unroll
            for (int j = 0; j < TP; j++) {
                float2 v = unpack2(acc[i][j]);
                if (EPI == 0) { v.x *= s; v.y *= s; }
                *(__half2*)(Chalf + row * BN + 2 * (tx + j * 16)) = __float22half2_rn(v);
            }
        }
    } else {  // EPI 2: BN=64, TP=2, full row across 16 lanes
        float2 b0 = *(const float2*)(biasC + 2 * tx);
        float2 b1 = *(const float2*)(biasC + 2 * (tx + 16));
#pragma unroll
        for (int i = 0; i < TM; i++) {
            int row = row0 + ty * TM + i;
            float2 v0 = unpack2(acc[i][0]);
            float2 v1 = unpack2(acc[i][1]);
            float t0 = v0.x + b0.x, t1 = v0.y + b0.y;
            float t2 = v1.x + b1.x, t3 = v1.y + b1.y;
            float m = fmaxf(fmaxf(t0, t1), fmaxf(t2, t3));
#pragma unroll
            for (int o = 8; o; o >>= 1) m = fmaxf(m, __shfl_xor_sync(0xFFFFFFFFu, m, o));
            float s = expf(t0 - m) + expf(t1 - m) + expf(t2 - m) + expf(t3 - m);
#pragma unroll
            for (int o = 8; o; o >>= 1) s += __shfl_xor_sync(0xFFFFFFFFu, s, o);
            float l = m + logf(s);
            if (row < M) {
                float2 r0, r1;
                r0.x = t0 - l; r0.y = t1 - l;
                r1.x = t2 - l; r1.y = t3 - l;
                *(float2*)(Cf + row * BN + 2 * tx)        = r0;
                *(float2*)(Cf + row * BN + 2 * (tx + 16)) = r1;
            }
        }
    }
}

// ---------------- CSR gather (fp16 messages) + finalize ----------------
// a = [dis-weighted] sum of fp16 message rows + self term (fp32 accum)
// h[v] = relu(dis[v]*a + bias)
// SCALE_MSG=1: messages unscaled (layer 1) -> weight by dis[s] / dis[v]
// SCALE_MSG=0: messages pre-scaled (layer 2)

template <bool SCALE_MSG>
__global__ __launch_bounds__(256)
void k_gather_fin(const __half* __restrict__ g, const float* __restrict__ dis,
                  const float* __restrict__ bias, float* __restrict__ h)
{
    int node = (blockIdx.x * blockDim.x + threadIdx.x) >> 5;
    int lane = threadIdx.x & 31;
    if (node >= NND) return;
    int beg = row_ptr[node];
    int end = row_ptr[node + 1];
    const uint2* gp = (const uint2*)g;   // 4 halves per lane, 32 lanes per row

    // self-loop message
    uint2 su = gp[node * 32 + lane];
    float2 f0 = __half22float2(*(__half2*)&su.x);
    float2 f1 = __half22float2(*(__half2*)&su.y);
    float4 a = make_float4(f0.x, f0.y, f1.x, f1.y);
    float dv = dis[node];
    if (SCALE_MSG) { a.x *= dv; a.y *= dv; a.z *= dv; a.w *= dv; }

    int e = beg;
    for (; e + 4 <= end; e += 4) {
        int s0 = __ldg(&csr_src[e + 0]);
        int s1 = __ldg(&csr_src[e + 1]);
        int s2 = __ldg(&csr_src[e + 2]);
        int s3 = __ldg(&csr_src[e + 3]);
        uint2 u0 = gp[s0 * 32 + lane];
        uint2 u1 = gp[s1 * 32 + lane];
        uint2 u2 = gp[s2 * 32 + lane];
        uint2 u3 = gp[s3 * 32 + lane];
        float2 a0 = __half22float2(*(__half2*)&u0.x), b0 = __half22float2(*(__half2*)&u0.y);
        float2 a1 = __half22float2(*(__half2*)&u1.x), b1 = __half22float2(*(__half2*)&u1.y);
        float2 a2 = __half22float2(*(__half2*)&u2.x), b2 = __half22float2(*(__half2*)&u2.y);
        float2 a3 = __half22float2(*(__half2*)&u3.x), b3 = __half22float2(*(__half2*)&u3.y);
        if (SCALE_MSG) {
            float d0 = __ldg(&dis[s0]), d1 = __ldg(&dis[s1]);
            float d2 = __ldg(&dis[s2]), d3 = __ldg(&dis[s3]);
            a.x = fmaf(a0.x, d0, a.x); a.y = fmaf(a0.y, d0, a.y);
            a.z = fmaf(b0.x, d0, a.z); a.w = fmaf(b0.y, d0, a.w);
            a.x = fmaf(a1.x, d1, a.x); a.y = fmaf(a1.y, d1, a.y);
            a.z = fmaf(b1.x, d1, a.z); a.w = fmaf(b1.y, d1, a.w);
            a.x = fmaf(a2.x, d2, a.x); a.y = fmaf(a2.y, d2, a.y);
            a.z = fmaf(b2.x, d2, a.z); a.w = fmaf(b2.y, d2, a.w);
            a.x = fmaf(a3.x, d3, a.x); a.y = fmaf(a3.y, d3, a.y);
            a.z = fmaf(b3.x, d3, a.z); a.w = fmaf(b3.y, d3, a.w);
        } else {
            a.x += a0.x + a1.x + a2.x + a3.x;
            a.y += a0.y + a1.y + a2.y + a3.y;
            a.z += b0.x + b1.x + b2.x + b3.x;
            a.w += b0.y + b1.y + b2.y + b3.y;
        }
    }
    for (; e < end; e++) {
        int s = __ldg(&csr_src[e]);
        uint2 u = gp[s * 32 + lane];
        float2 p0 = __half22float2(*(__half2*)&u.x);
        float2 p1 = __half22float2(*(__half2*)&u.y);
        if (SCALE_MSG) {
            float ds = __ldg(&dis[s]);
            a.x = fmaf(p0.x, ds, a.x); a.y = fmaf(p0.y, ds, a.y);
            a.z = fmaf(p1.x, ds, a.z); a.w = fmaf(p1.y, ds, a.w);
        } else {
            a.x += p0.x; a.y += p0.y; a.z += p1.x; a.w += p1.y;
        }
    }
    // finalize: relu(dis[v]*a + bias)
    float4 b = ((const float4*)bias)[lane];
    float4 r;
    r.x = fmaxf(fmaf(a.x, dv, b.x), 0.f);
    r.y = fmaxf(fmaf(a.y, dv, b.y), 0.f);
    r.z = fmaxf(fmaf(a.z, dv, b.z), 0.f);
    r.w = fmaxf(fmaf(a.w, dv, b.w), 0.f);
    ((float4*)h)[node * 32 + lane] = r;
}

// ---------------- launch ----------------

extern "C" void kernel_launch(void* const* d_in, const int* in_sizes, int n_in,
                              void* d_out, int out_size)
{
    const float* x   = (const float*)d_in[0];
    const int*   ei  = (const int*)d_in[1];
    const int*   src = ei;
    const int*   dst = ei + NE;
    const float* W1  = (const float*)d_in[2];
    const float* b1  = (const float*)d_in[3];
    const float* W2  = (const float*)d_in[4];
    const float* b2  = (const float*)d_in[5];
    const float* Wp1 = (const float*)d_in[6];
    const float* bp1 = (const float*)d_in[7];
    const float* Wp2 = (const float*)d_in[8];
    const float* bp2 = (const float*)d_in[9];
    float* out = (float*)d_out;

    __half *g_p, *g2_p;
    float *acc_p, *dis_p, *wf_p, *bf_p;
    cudaGetSymbolAddress((void**)&g_p,   g_buf);
    cudaGetSymbolAddress((void**)&g2_p,  g2_buf);
    cudaGetSymbolAddress((void**)&acc_p, acc_buf);
    cudaGetSymbolAddress((void**)&dis_p, dis_buf);
    cudaGetSymbolAddress((void**)&wf_p,  Wf_buf);
    cudaGetSymbolAddress((void**)&bf_p,  bF_buf);

    // streams/events created once, outside any graph capture
    static cudaStream_t s2 = nullptr;
    static cudaEvent_t ev_fork, ev_csr;
    if (!s2) {
        cudaStreamCreateWithFlags(&s2, cudaStreamNonBlocking);
        cudaEventCreateWithFlags(&ev_fork, cudaEventDisableTiming);
        cudaEventCreateWithFlags(&ev_csr,  cudaEventDisableTiming);
    }

    const int GEMM_BLOCKS   = (NND + 127) / 128;       // 782
    const int GATHER_BLOCKS = (NND * 32 + 255) / 256;  // 12500

    // ---- fork: CSR build + norm + head-weight fusion on s2, GEMM1 on main ----
    cudaEventRecord(ev_fork, 0);
    cudaStreamWaitEvent(s2, ev_fork, 0);

    k_fusew<<<(D * 64 + 255) / 256, 256, 0, s2>>>(Wp1, bp1, Wp2, bp2);
    k_init_deg<<<(NND + 255) / 256, 256, 0, s2>>>();
    k_count_deg<<<(NE + 255) / 256, 256, 0, s2>>>(dst);
    k_dis<<<(NND + 255) / 256, 256, 0, s2>>>();
    k_scan1<<<SCAN_BLOCKS, SCB, 0, s2>>>();
    k_scan2<<<1, 256, 0, s2>>>();
    k_scan3<<<SCAN_BLOCKS, SCB, 0, s2>>>();
    k_fill<<<(NE + 255) / 256, 256, 0, s2>>>(src, dst);
    cudaEventRecord(ev_csr, s2);

    // GEMM1 (main): g = half(x@W1)  (plain, no dis dependency)
    gemm_k128<128, 8, 3><<<GEMM_BLOCKS, 256>>>(
        x, W1, nullptr, nullptr, g_p, nullptr, NND);

    cudaStreamWaitEvent(0, ev_csr, 0);

    // ---- layer 1 aggregate: h = relu(dis*(dis-weighted gather of g) + b1) ----
    k_gather_fin<true><<<GATHER_BLOCKS, 256>>>(g_p, dis_p, b1, acc_p);

    // ---- GCN layer 2: g2 = half((h@W2)*dis) ; h = relu(dis*gather(g2) + b2) ----
    gemm_k128<128, 8, 0><<<GEMM_BLOCKS, 256>>>(
        acc_p, W2, nullptr, dis_p, g2_p, nullptr, NND);
    k_gather_fin<false><<<GATHER_BLOCKS, 256>>>(g2_p, dis_p, b2, acc_p);

    // ---- fused head + log_softmax: out = logsoftmax(h @ Wf + bF) ----
    gemm_k128<64, 4, 2><<<GEMM_BLOCKS, 256>>>(
        acc_p, wf_p, bf_p, dis_p, nullptr, out, NND);
}

// round 9
// speedup vs baseline: 2.0564x; 1.5950x over previous
#include <cuda_runtime.h>
#include <cuda_fp16.h>
#include <math.h>
#include <stdint.h>

#define NND 100000
#define NE  1600000
#define D   128

// Scratch (static device globals — no runtime allocation allowed)
__device__ __half g_buf [NND * D];   // layer-1 messages (fp16)
__device__ __half g2_buf[NND * D];   // layer-2 messages (fp16)
__device__ __half h_buf [NND * D];   // activations (fp16)
__device__ float dis_buf[NND];
__device__ int   deg_buf[NND];
__device__ int   scan_tmp[NND];
__device__ int   row_ptr[NND + 1];
__device__ int   cursor[NND];
__device__ int   csr_src[NE];
__device__ int   bsum[256];
__device__ __half W1h_buf[D * D];
__device__ __half W2h_buf[D * D];
__device__ __half Wfh_buf[D * 64];   // fused head weight  Wp1@Wp2 (fp16)
__device__ float bF_buf[64];         // fused head bias    bp1@Wp2 + bp2

// ---------------- degree / normalization / CSR build ----------------

__global__ void k_init_deg() {
    int i = blockIdx.x * blockDim.x + threadIdx.x;
    if (i < NND) deg_buf[i] = 0;
}

__global__ void k_count_deg(const int* __restrict__ dst) {
    int e = blockIdx.x * blockDim.x + threadIdx.x;
    if (e < NE) atomicAdd(&deg_buf[dst[e]], 1);
}

__global__ void k_dis() {
    int i = blockIdx.x * blockDim.x + threadIdx.x;
    if (i < NND) dis_buf[i] = rsqrtf((float)(deg_buf[i] + 1));
}

#define SCB 512
#define SCAN_BLOCKS ((NND + SCB - 1) / SCB)   // 196

__global__ __launch_bounds__(SCB) void k_scan1() {
    __shared__ int sm[SCB];
    int i = blockIdx.x * SCB + threadIdx.x;
    int v = (i < NND) ? deg_buf[i] : 0;
    sm[threadIdx.x] = v;
    __syncthreads();
#pragma unroll
    for (int off = 1; off < SCB; off <<= 1) {
        int t = (threadIdx.x >= off) ? sm[threadIdx.x - off] : 0;
        __syncthreads();
        sm[threadIdx.x] += t;
        __syncthreads();
    }
    if (i < NND) scan_tmp[i] = sm[threadIdx.x];
    if (threadIdx.x == SCB - 1) bsum[blockIdx.x] = sm[SCB - 1];
}

__global__ __launch_bounds__(256) void k_scan2() {
    __shared__ int sm[256];
    int v = (threadIdx.x < SCAN_BLOCKS) ? bsum[threadIdx.x] : 0;
    sm[threadIdx.x] = v;
    __syncthreads();
#pragma unroll
    for (int off = 1; off < 256; off <<= 1) {
        int t = (threadIdx.x >= off) ? sm[threadIdx.x - off] : 0;
        __syncthreads();
        sm[threadIdx.x] += t;
        __syncthreads();
    }
    bsum[threadIdx.x] = sm[threadIdx.x];  // inclusive
}

__global__ __launch_bounds__(SCB) void k_scan3() {
    int i = blockIdx.x * SCB + threadIdx.x;
    if (i >= NND) return;
    int off = (blockIdx.x > 0) ? bsum[blockIdx.x - 1] : 0;
    int inc = scan_tmp[i] + off;
    int st  = inc - deg_buf[i];
    row_ptr[i] = st;
    cursor[i]  = st;
    if (i == NND - 1) row_ptr[NND] = inc;
}

__global__ void k_fill(const int* __restrict__ src, const int* __restrict__ dst) {
    int e = blockIdx.x * blockDim.x + threadIdx.x;
    if (e >= NE) return;
    int p = atomicAdd(&cursor[dst[e]], 1);
    csr_src[p] = src[e];
}

// ---------------- weight conversion / head fusion ----------------

__global__ void k_convW(const float* __restrict__ W, __half* __restrict__ Wh, int n) {
    int i = blockIdx.x * blockDim.x + threadIdx.x;
    if (i < n) Wh[i] = __float2half_rn(W[i]);
}

__global__ __launch_bounds__(256) void k_fusew(const float* __restrict__ Wp1,
                                               const float* __restrict__ bp1,
                                               const float* __restrict__ Wp2,
                                               const float* __restrict__ bp2)
{
    int i = blockIdx.x * blockDim.x + threadIdx.x;
    if (i >= D * 64) return;
    int k = i >> 6, n = i & 63;
    float s = 0.0f;
#pragma unroll 8
    for (int j = 0; j < D; j++)
        s = fmaf(Wp1[k * D + j], Wp2[j * 64 + n], s);
    Wfh_buf[i] = __float2half_rn(s);
    if (k == 0) {
        float t = bp2[n];
#pragma unroll 8
        for (int j = 0; j < D; j++)
            t = fmaf(bp1[j], Wp2[j * 64 + n], t);
        bF_buf[n] = t;
    }
}

// ---------------- HMMA GEMM: C[rows,BN] = A[rows,128] @ W[128,BN] + epilogue ----------
// 256 threads = 8 warps; warp w owns rows [w*16, w*16+16); mma.sync m16n8k16 fp16->fp32.
// A_HALF: A is fp16 (h_buf) else fp32 (converted on load).
// EPI 0: Chalf = half(acc * dis[row])     EPI 3: Chalf = half(acc)
// EPI 2: Cf = log_softmax(acc + biasC) over row (BN=64)

template <int BN, bool A_HALF, int EPI>
__global__ __launch_bounds__(256)
void hgemm(const void* __restrict__ Ain,
           const __half* __restrict__ Wh,
           const float* __restrict__ biasC,
           const float* __restrict__ dis,
           __half* __restrict__ Chalf,
           float* __restrict__ Cf)
{
    constexpr int KC  = 32;
    constexpr int SAH = KC + 8;       // 40 halves (80 B) — conflict-free LDSM
    constexpr int SBH = BN + 8;       // 136 / 72 halves
    constexpr int NT  = BN / 8;       // n8 tiles per row strip
    __shared__ __align__(16) __half As[128 * SAH];
    __shared__ __align__(16) __half Ws[KC * SBH];

    const int tid  = threadIdx.x;
    const int wid  = tid >> 5;
    const int lane = tid & 31;
    const int row0 = blockIdx.x * 128;
    const int wr0  = wid * 16;

    float c[NT][4];
#pragma unroll
    for (int j = 0; j < NT; j++)
#pragma unroll
        for (int q = 0; q < 4; q++) c[j][q] = 0.0f;

    const uint32_t as_base = (uint32_t)__cvta_generic_to_shared(As);
    const uint32_t ws_base = (uint32_t)__cvta_generic_to_shared(Ws);
    // per-lane ldmatrix address components
    const uint32_t a_lane = ((wr0 + (lane & 15)) * SAH + (lane >> 4) * 8) * 2;
    const uint32_t b_lane_row = (lane & 15);
    const uint32_t b_lane_col = ((lane & 16) >> 1);

    for (int kc = 0; kc < 128; kc += KC) {
        // ---- load A chunk (128 x KC) ----
        if (A_HALF) {
            const __half* Ah = (const __half*)Ain;
#pragma unroll
            for (int p = 0; p < 2; p++) {
                int i = tid + p * 256;
                int r = i >> 2, c8 = i & 3;
                int row = row0 + r;
                uint4 v = make_uint4(0, 0, 0, 0);
                if (row < NND)
                    v = *(const uint4*)(Ah + row * D + kc + c8 * 8);
                *(uint4*)(As + r * SAH + c8 * 8) = v;
            }
        } else {
            const float* Af = (const float*)Ain;
#pragma unroll
            for (int p = 0; p < 4; p++) {
                int i = tid + p * 256;
                int r = i >> 3, c4 = i & 7;
                int row = row0 + r;
                float4 v = make_float4(0.f, 0.f, 0.f, 0.f);
                if (row < NND)
                    v = *(const float4*)(Af + row * D + kc + c4 * 4);
                __half2 h01 = __floats2half2_rn(v.x, v.y);
                __half2 h23 = __floats2half2_rn(v.z, v.w);
                uint2 u;
                u.x = *(uint32_t*)&h01;
                u.y = *(uint32_t*)&h23;
                *(uint2*)(As + r * SAH + c4 * 4) = u;
            }
        }
        // ---- load W chunk (KC x BN) ----
#pragma unroll
        for (int p = 0; p < (KC * BN / 8) / 256; p++) {
            int i = tid + p * 256;
            int r = i / (BN / 8), c8 = i % (BN / 8);
            *(uint4*)(Ws + r * SBH + c8 * 8) = *(const uint4*)(Wh + (kc + r) * BN + c8 * 8);
        }
        __syncthreads();

        // ---- compute: two k16 steps per chunk ----
#pragma unroll
        for (int kk = 0; kk < KC; kk += 16) {
            uint32_t a0, a1, a2, a3;
            uint32_t aaddr = as_base + a_lane + kk * 2;
            asm volatile("ldmatrix.sync.aligned.m8n8.x4.shared.b16 {%0,%1,%2,%3}, [%4];"
                         : "=r"(a0), "=r"(a1), "=r"(a2), "=r"(a3) : "r"(aaddr));
#pragma unroll
            for (int jt = 0; jt < NT / 2; jt++) {
                uint32_t b0, b1, b2, b3;
                uint32_t baddr = ws_base +
                    ((kk + b_lane_row) * SBH + jt * 16 + b_lane_col) * 2;
                asm volatile("ldmatrix.sync.aligned.m8n8.x4.trans.shared.b16 {%0,%1,%2,%3}, [%4];"
                             : "=r"(b0), "=r"(b1), "=r"(b2), "=r"(b3) : "r"(baddr));
                asm volatile("mma.sync.aligned.m16n8k16.row.col.f32.f16.f16.f32 "
                             "{%0,%1,%2,%3},{%4,%5,%6,%7},{%8,%9},{%0,%1,%2,%3};"
                             : "+f"(c[2*jt][0]), "+f"(c[2*jt][1]),
                               "+f"(c[2*jt][2]), "+f"(c[2*jt][3])
                             : "r"(a0), "r"(a1), "r"(a2), "r"(a3), "r"(b0), "r"(b1));
                asm volatile("mma.sync.aligned.m16n8k16.row.col.f32.f16.f16.f32 "
                             "{%0,%1,%2,%3},{%4,%5,%6,%7},{%8,%9},{%0,%1,%2,%3};"
                             : "+f"(c[2*jt+1][0]), "+f"(c[2*jt+1][1]),
                               "+f"(c[2*jt+1][2]), "+f"(c[2*jt+1][3])
                             : "r"(a0), "r"(a1), "r"(a2), "r"(a3), "r"(b2), "r"(b3));
            }
        }
        __syncthreads();
    }

    // fragment rows
    const int r1 = row0 + wr0 + (lane >> 2);
    const int r2 = r1 + 8;

    if (EPI == 0 || EPI == 3) {
        float s1 = 1.0f, s2 = 1.0f;
        if (EPI == 0) {
            if (r1 < NND) s1 = dis[r1];
            if (r2 < NND) s2 = dis[r2];
        }
#pragma unroll
        for (int j = 0; j < NT; j++) {
            int col = j * 8 + (lane & 3) * 2;
            if (r1 < NND)
                *(__half2*)(Chalf + r1 * BN + col) =
                    __floats2half2_rn(c[j][0] * s1, c[j][1] * s1);
            if (r2 < NND)
                *(__half2*)(Chalf + r2 * BN + col) =
                    __floats2half2_rn(c[j][2] * s2, c[j][3] * s2);
        }
    } else {  // EPI 2: BN=64, NT=8, log_softmax per row
        float t[8][4];
        float m1 = -1e30f, m2 = -1e30f;
#pragma unroll
        for (int j = 0; j < NT; j++) {
            float2 b = *(const float2*)(biasC + j * 8 + (lane & 3) * 2);
            t[j][0] = c[j][0] + b.x; t[j][1] = c[j][1] + b.y;
            t[j][2] = c[j][2] + b.x; t[j][3] = c[j][3] + b.y;
            m1 = fmaxf(m1, fmaxf(t[j][0], t[j][1]));
            m2 = fmaxf(m2, fmaxf(t[j][2], t[j][3]));
        }
#pragma unroll
        for (int o = 1; o <= 2; o <<= 1) {
            m1 = fmaxf(m1, __shfl_xor_sync(0xFFFFFFFFu, m1, o));
            m2 = fmaxf(m2, __shfl_xor_sync(0xFFFFFFFFu, m2, o));
        }
        float s1 = 0.f, s2 = 0.f;
#pragma unroll
        for (int j = 0; j < NT; j++) {
            s1 += expf(t[j][0] - m1) + expf(t[j][1] - m1);
            s2 += expf(t[j][2] - m2) + expf(t[j][3] - m2);
        }
#pragma unroll
        for (int o = 1; o <= 2; o <<= 1) {
            s1 += __shfl_xor_sync(0xFFFFFFFFu, s1, o);
            s2 += __shfl_xor_sync(0xFFFFFFFFu, s2, o);
        }
        float l1 = m1 + logf(s1);
        float l2 = m2 + logf(s2);
#pragma unroll
        for (int j = 0; j < NT; j++) {
            int col = j * 8 + (lane & 3) * 2;
            if (r1 < NND) {
                float2 r; r.x = t[j][0] - l1; r.y = t[j][1] - l1;
                *(float2*)(Cf + r1 * BN + col) = r;
            }
            if (r2 < NND) {
                float2 r; r.x = t[j][2] - l2; r.y = t[j][3] - l2;
                *(float2*)(Cf + r2 * BN + col) = r;
            }
        }
    }
}

// ---------------- CSR gather (fp16 messages) + finalize -> fp16 h ----------------
// SCALE_MSG=1: weight messages by dis[s] (layer 1); 0: pre-scaled (layer 2)
// h[v] = half(relu(dis[v]*a + bias))

template <bool SCALE_MSG>
__global__ __launch_bounds__(256)
void k_gather_fin(const __half* __restrict__ g, const float* __restrict__ dis,
                  const float* __restrict__ bias, __half* __restrict__ h)
{
    int node = (blockIdx.x * blockDim.x + threadIdx.x) >> 5;
    int lane = threadIdx.x & 31;
    if (node >= NND) return;
    int beg = row_ptr[node];
    int end = row_ptr[node + 1];
    const uint2* gp = (const uint2*)g;   // 4 halves per lane

    uint2 su = gp[node * 32 + lane];
    float2 f0 = __half22float2(*(__half2*)&su.x);
    float2 f1 = __half22float2(*(__half2*)&su.y);
    float4 a = make_float4(f0.x, f0.y, f1.x, f1.y);
    float dv = dis[node];
    if (SCALE_MSG) { a.x *= dv; a.y *= dv; a.z *= dv; a.w *= dv; }

    int e = beg;
    for (; e + 4 <= end; e += 4) {
        int s0 = __ldg(&csr_src[e + 0]);
        int s1 = __ldg(&csr_src[e + 1]);
        int s2 = __ldg(&csr_src[e + 2]);
        int s3 = __ldg(&csr_src[e + 3]);
        uint2 u0 = gp[s0 * 32 + lane];
        uint2 u1 = gp[s1 * 32 + lane];
        uint2 u2 = gp[s2 * 32 + lane];
        uint2 u3 = gp[s3 * 32 + lane];
        float2 a0 = __half22float2(*(__half2*)&u0.x), b0 = __half22float2(*(__half2*)&u0.y);
        float2 a1 = __half22float2(*(__half2*)&u1.x), b1 = __half22float2(*(__half2*)&u1.y);
        float2 a2 = __half22float2(*(__half2*)&u2.x), b2 = __half22float2(*(__half2*)&u2.y);
        float2 a3 = __half22float2(*(__half2*)&u3.x), b3 = __half22float2(*(__half2*)&u3.y);
        if (SCALE_MSG) {
            float d0 = __ldg(&dis[s0]), d1 = __ldg(&dis[s1]);
            float d2 = __ldg(&dis[s2]), d3 = __ldg(&dis[s3]);
            a.x = fmaf(a0.x, d0, a.x); a.y = fmaf(a0.y, d0, a.y);
            a.z = fmaf(b0.x, d0, a.z); a.w = fmaf(b0.y, d0, a.w);
            a.x = fmaf(a1.x, d1, a.x); a.y = fmaf(a1.y, d1, a.y);
            a.z = fmaf(b1.x, d1, a.z); a.w = fmaf(b1.y, d1, a.w);
            a.x = fmaf(a2.x, d2, a.x); a.y = fmaf(a2.y, d2, a.y);
            a.z = fmaf(b2.x, d2, a.z); a.w = fmaf(b2.y, d2, a.w);
            a.x = fmaf(a3.x, d3, a.x); a.y = fmaf(a3.y, d3, a.y);
            a.z = fmaf(b3.x, d3, a.z); a.w = fmaf(b3.y, d3, a.w);
        } else {
            a.x += a0.x + a1.x + a2.x + a3.x;
            a.y += a0.y + a1.y + a2.y + a3.y;
            a.z += b0.x + b1.x + b2.x + b3.x;
            a.w += b0.y + b1.y + b2.y + b3.y;
        }
    }
    for (; e < end; e++) {
        int s = __ldg(&csr_src[e]);
        uint2 u = gp[s * 32 + lane];
        float2 p0 = __half22float2(*(__half2*)&u.x);
        float2 p1 = __half22float2(*(__half2*)&u.y);
        if (SCALE_MSG) {
            float ds = __ldg(&dis[s]);
            a.x = fmaf(p0.x, ds, a.x); a.y = fmaf(p0.y, ds, a.y);
            a.z = fmaf(p1.x, ds, a.z); a.w = fmaf(p1.y, ds, a.w);
        } else {
            a.x += p0.x; a.y += p0.y; a.z += p1.x; a.w += p1.y;
        }
    }
    float4 b = ((const float4*)bias)[lane];
    __half2 r0 = __floats2half2_rn(fmaxf(fmaf(a.x, dv, b.x), 0.f),
                                   fmaxf(fmaf(a.y, dv, b.y), 0.f));
    __half2 r1 = __floats2half2_rn(fmaxf(fmaf(a.z, dv, b.z), 0.f),
                                   fmaxf(fmaf(a.w, dv, b.w), 0.f));
    uint2 u;
    u.x = *(uint32_t*)&r0;
    u.y = *(uint32_t*)&r1;
    ((uint2*)h)[node * 32 + lane] = u;
}

// ---------------- launch ----------------

extern "C" void kernel_launch(void* const* d_in, const int* in_sizes, int n_in,
                              void* d_out, int out_size)
{
    const float* x   = (const float*)d_in[0];
    const int*   ei  = (const int*)d_in[1];
    const int*   src = ei;
    const int*   dst = ei + NE;
    const float* W1  = (const float*)d_in[2];
    const float* b1  = (const float*)d_in[3];
    const float* W2  = (const float*)d_in[4];
    const float* b2  = (const float*)d_in[5];
    const float* Wp1 = (const float*)d_in[6];
    const float* bp1 = (const float*)d_in[7];
    const float* Wp2 = (const float*)d_in[8];
    const float* bp2 = (const float*)d_in[9];
    float* out = (float*)d_out;

    __half *g_p, *g2_p, *h_p, *w1h_p, *w2h_p, *wfh_p;
    float *dis_p, *bf_p;
    cudaGetSymbolAddress((void**)&g_p,   g_buf);
    cudaGetSymbolAddress((void**)&g2_p,  g2_buf);
    cudaGetSymbolAddress((void**)&h_p,   h_buf);
    cudaGetSymbolAddress((void**)&dis_p, dis_buf);
    cudaGetSymbolAddress((void**)&w1h_p, W1h_buf);
    cudaGetSymbolAddress((void**)&w2h_p, W2h_buf);
    cudaGetSymbolAddress((void**)&wfh_p, Wfh_buf);
    cudaGetSymbolAddress((void**)&bf_p,  bF_buf);

    static cudaStream_t s2 = nullptr;
    static cudaEvent_t ev_fork, ev_csr;
    if (!s2) {
        cudaStreamCreateWithFlags(&s2, cudaStreamNonBlocking);
        cudaEventCreateWithFlags(&ev_fork, cudaEventDisableTiming);
        cudaEventCreateWithFlags(&ev_csr,  cudaEventDisableTiming);
    }

    const int GEMM_BLOCKS   = (NND + 127) / 128;       // 782
    const int GATHER_BLOCKS = (NND * 32 + 255) / 256;  // 12500

    // ---- fork: CSR build + norm + weight prep on s2 ----
    cudaEventRecord(ev_fork, 0);
    cudaStreamWaitEvent(s2, ev_fork, 0);

    k_fusew<<<(D * 64 + 255) / 256, 256, 0, s2>>>(Wp1, bp1, Wp2, bp2);
    k_convW<<<(D * D + 255) / 256, 256, 0, s2>>>(W2, w2h_p, D * D);
    k_init_deg<<<(NND + 255) / 256, 256, 0, s2>>>();
    k_count_deg<<<(NE + 255) / 256, 256, 0, s2>>>(dst);
    k_dis<<<(NND + 255) / 256, 256, 0, s2>>>();
    k_scan1<<<SCAN_BLOCKS, SCB, 0, s2>>>();
    k_scan2<<<1, 256, 0, s2>>>();
    k_scan3<<<SCAN_BLOCKS, SCB, 0, s2>>>();
    k_fill<<<(NE + 255) / 256, 256, 0, s2>>>(src, dst);
    cudaEventRecord(ev_csr, s2);

    // main: convert W1, then GEMM1: g = half(x@W1)
    k_convW<<<(D * D + 255) / 256, 256>>>(W1, w1h_p, D * D);
    hgemm<128, false, 3><<<GEMM_BLOCKS, 256>>>(
        x, w1h_p, nullptr, nullptr, g_p, nullptr);

    cudaStreamWaitEvent(0, ev_csr, 0);

    // ---- layer 1 aggregate: h = half(relu(dis*(dis-weighted gather g) + b1)) ----
    k_gather_fin<true><<<GATHER_BLOCKS, 256>>>(g_p, dis_p, b1, h_p);

    // ---- layer 2: g2 = half((h@W2)*dis) ; h = half(relu(dis*gather(g2) + b2)) ----
    hgemm<128, true, 0><<<GEMM_BLOCKS, 256>>>(
        h_p, w2h_p, nullptr, dis_p, g2_p, nullptr);
    k_gather_fin<false><<<GATHER_BLOCKS, 256>>>(g2_p, dis_p, b2, h_p);

    // ---- fused head + log_softmax: out = logsoftmax(h @ Wf + bF) ----
    hgemm<64, true, 2><<<GEMM_BLOCKS, 256>>>(
        h_p, wfh_p, bf_p, dis_p, nullptr, out);
}

// round 10
// speedup vs baseline: 2.1694x; 1.0549x over previous
#include <cuda_runtime.h>
#include <cuda_fp16.h>
#include <math.h>
#include <stdint.h>

#define NND 100000
#define NE  1600000
#define D   128

// Scratch (static device globals — no runtime allocation allowed)
__device__ __half g_buf [NND * D];   // layer-1 messages (fp16)
__device__ __half g2_buf[NND * D];   // layer-2 messages (fp16)
__device__ __half h_buf [NND * D];   // activations (fp16)
__device__ float dis_buf[NND];
__device__ int   deg_buf[NND];
__device__ int   scan_tmp[NND];
__device__ int   row_ptr[NND + 1];
__device__ int   cursor[NND];
__device__ int   csr_src[NE];
__device__ int   bsum[256];
__device__ __half W1h_buf[D * D];
__device__ __half W2h_buf[D * D];
__device__ __half Wfh_buf[D * 64];   // fused head weight  Wp1@Wp2 (fp16)
__device__ float bF_buf[64];         // fused head bias    bp1@Wp2 + bp2

// ---------------- cp.async helpers ----------------

__device__ __forceinline__ void cp_async16(uint32_t saddr, const void* gaddr, int szbytes) {
    asm volatile("cp.async.cg.shared.global [%0], [%1], 16, %2;"
                 :: "r"(saddr), "l"(gaddr), "r"(szbytes));
}
__device__ __forceinline__ void cp_async_commit_wait() {
    asm volatile("cp.async.commit_group;");
    asm volatile("cp.async.wait_group 0;");
}

// ---------------- degree / normalization / CSR build ----------------

__global__ void k_init_deg() {
    int i = blockIdx.x * blockDim.x + threadIdx.x;
    if (i < NND) deg_buf[i] = 0;
}

// 4 edges per thread (int4) — MLP=4, streams dst at DRAM BW
__global__ void k_count_deg(const int* __restrict__ dst) {
    int t = blockIdx.x * blockDim.x + threadIdx.x;
    if (t * 4 >= NE) return;
    int4 d = *(const int4*)(dst + t * 4);
    atomicAdd(&deg_buf[d.x], 1);
    atomicAdd(&deg_buf[d.y], 1);
    atomicAdd(&deg_buf[d.z], 1);
    atomicAdd(&deg_buf[d.w], 1);
}

#define SCB 512
#define SCAN_BLOCKS ((NND + SCB - 1) / SCB)   // 196

__global__ __launch_bounds__(SCB) void k_scan1() {
    __shared__ int sm[SCB];
    int i = blockIdx.x * SCB + threadIdx.x;
    int v = (i < NND) ? deg_buf[i] : 0;
    sm[threadIdx.x] = v;
    __syncthreads();
#pragma unroll
    for (int off = 1; off < SCB; off <<= 1) {
        int t = (threadIdx.x >= off) ? sm[threadIdx.x - off] : 0;
        __syncthreads();
        sm[threadIdx.x] += t;
        __syncthreads();
    }
    if (i < NND) scan_tmp[i] = sm[threadIdx.x];
    if (threadIdx.x == SCB - 1) bsum[blockIdx.x] = sm[SCB - 1];
}

__global__ __launch_bounds__(256) void k_scan2() {
    __shared__ int sm[256];
    int v = (threadIdx.x < SCAN_BLOCKS) ? bsum[threadIdx.x] : 0;
    sm[threadIdx.x] = v;
    __syncthreads();
#pragma unroll
    for (int off = 1; off < 256; off <<= 1) {
        int t = (threadIdx.x >= off) ? sm[threadIdx.x - off] : 0;
        __syncthreads();
        sm[threadIdx.x] += t;
        __syncthreads();
    }
    bsum[threadIdx.x] = sm[threadIdx.x];  // inclusive
}

// scan3 + dis fused (dis = rsqrt(deg+1))
__global__ __launch_bounds__(SCB) void k_scan3() {
    int i = blockIdx.x * SCB + threadIdx.x;
    if (i >= NND) return;
    int dg  = deg_buf[i];
    int off = (blockIdx.x > 0) ? bsum[blockIdx.x - 1] : 0;
    int inc = scan_tmp[i] + off;
    int st  = inc - dg;
    row_ptr[i] = st;
    cursor[i]  = st;
    dis_buf[i] = rsqrtf((float)(dg + 1));
    if (i == NND - 1) row_ptr[NND] = inc;
}

// 4 edges per thread
__global__ void k_fill(const int* __restrict__ src, const int* __restrict__ dst) {
    int t = blockIdx.x * blockDim.x + threadIdx.x;
    if (t * 4 >= NE) return;
    int4 s = *(const int4*)(src + t * 4);
    int4 d = *(const int4*)(dst + t * 4);
    csr_src[atomicAdd(&cursor[d.x], 1)] = s.x;
    csr_src[atomicAdd(&cursor[d.y], 1)] = s.y;
    csr_src[atomicAdd(&cursor[d.z], 1)] = s.z;
    csr_src[atomicAdd(&cursor[d.w], 1)] = s.w;
}

// ---------------- weight conversion / head fusion ----------------

__global__ void k_convW(const float* __restrict__ W, __half* __restrict__ Wh, int n) {
    int i = blockIdx.x * blockDim.x + threadIdx.x;
    if (i < n) Wh[i] = __float2half_rn(W[i]);
}

__global__ __launch_bounds__(256) void k_fusew(const float* __restrict__ Wp1,
                                               const float* __restrict__ bp1,
                                               const float* __restrict__ Wp2,
                                               const float* __restrict__ bp2)
{
    int i = blockIdx.x * blockDim.x + threadIdx.x;
    if (i >= D * 64) return;
    int k = i >> 6, n = i & 63;
    float s = 0.0f;
#pragma unroll 8
    for (int j = 0; j < D; j++)
        s = fmaf(Wp1[k * D + j], Wp2[j * 64 + n], s);
    Wfh_buf[i] = __float2half_rn(s);
    if (k == 0) {
        float t = bp2[n];
#pragma unroll 8
        for (int j = 0; j < D; j++)
            t = fmaf(bp1[j], Wp2[j * 64 + n], t);
        bF_buf[n] = t;
    }
}

// ---------------- HMMA GEMM (full-K resident): C = A[128rows,128] @ W[128,BN] --------
// 256 threads = 8 warps; warp w owns rows [w*16, w*16+16); mma.sync m16n8k16 fp16->fp32.
// A and W fully staged in dynamic smem (cp.async), one barrier, 8 uninterrupted k-steps.
// EPI 0: Chalf = half(acc * dis[row])     EPI 3: Chalf = half(acc)
// EPI 2: Cf = log_softmax(acc + biasC) over row (BN=64)

template <int BN, bool A_HALF, int EPI>
__global__ __launch_bounds__(256)
void hgemm(const void* __restrict__ Ain,
           const __half* __restrict__ Wh,
           const float* __restrict__ biasC,
           const float* __restrict__ dis,
           __half* __restrict__ Chalf,
           float* __restrict__ Cf)
{
    constexpr int SAH = D + 8;        // 136 halves (272 B row) — conflict-free LDSM
    constexpr int SBH = BN + 8;       // 136 / 72 halves
    constexpr int NT  = BN / 8;       // n8 tiles per row strip
    extern __shared__ __align__(16) __half smem[];
    __half* As = smem;                 // 128 * SAH
    __half* Ws = smem + 128 * SAH;     // 128 * SBH

    const int tid  = threadIdx.x;
    const int wid  = tid >> 5;
    const int lane = tid & 31;
    const int row0 = blockIdx.x * 128;
    const int wr0  = wid * 16;

    const uint32_t as_base = (uint32_t)__cvta_generic_to_shared(As);
    const uint32_t ws_base = (uint32_t)__cvta_generic_to_shared(Ws);

    // ---- stage A (128 x 128 halves) ----
    if (A_HALF) {
        const __half* Ah = (const __half*)Ain;
#pragma unroll
        for (int p = 0; p < 8; p++) {
            int i  = tid + p * 256;          // 2048 16B-chunks
            int r  = i >> 4, c8 = i & 15;
            int row = row0 + r;
            uint32_t saddr = as_base + (r * SAH + c8 * 8) * 2;
            const __half* gaddr = Ah + (row < NND ? row : 0) * D + c8 * 8;
            cp_async16(saddr, gaddr, row < NND ? 16 : 0);
        }
    } else {
        const float* Af = (const float*)Ain;
#pragma unroll
        for (int p = 0; p < 16; p++) {
            int i  = tid + p * 256;          // 4096 float4-chunks
            int r  = i >> 5, c4 = i & 31;
            int row = row0 + r;
            float4 v = make_float4(0.f, 0.f, 0.f, 0.f);
            if (row < NND)
                v = *(const float4*)(Af + row * D + c4 * 4);
            __half2 h01 = __floats2half2_rn(v.x, v.y);
            __half2 h23 = __floats2half2_rn(v.z, v.w);
            uint2 u;
            u.x = *(uint32_t*)&h01;
            u.y = *(uint32_t*)&h23;
            *(uint2*)(As + r * SAH + c4 * 4) = u;
        }
    }
    // ---- stage W (128 x BN halves) ----
#pragma unroll
    for (int p = 0; p < (D * BN / 8) / 256; p++) {
        int i = tid + p * 256;
        int r = i / (BN / 8), c8 = i % (BN / 8);
        cp_async16(ws_base + (r * SBH + c8 * 8) * 2, Wh + r * BN + c8 * 8, 16);
    }
    cp_async_commit_wait();
    __syncthreads();

    float c[NT][4];
#pragma unroll
    for (int j = 0; j < NT; j++)
#pragma unroll
        for (int q = 0; q < 4; q++) c[j][q] = 0.0f;

    const uint32_t a_lane = ((wr0 + (lane & 15)) * SAH + (lane >> 4) * 8) * 2;
    const uint32_t b_lane_row = (lane & 15);
    const uint32_t b_lane_col = ((lane & 16) >> 1);

#pragma unroll
    for (int kk = 0; kk < D; kk += 16) {
        uint32_t a0, a1, a2, a3;
        uint32_t aaddr = as_base + a_lane + kk * 2;
        asm volatile("ldmatrix.sync.aligned.m8n8.x4.shared.b16 {%0,%1,%2,%3}, [%4];"
                     : "=r"(a0), "=r"(a1), "=r"(a2), "=r"(a3) : "r"(aaddr));
#pragma unroll
        for (int jt = 0; jt < NT / 2; jt++) {
            uint32_t b0, b1, b2, b3;
            uint32_t baddr = ws_base +
                ((kk + b_lane_row) * SBH + jt * 16 + b_lane_col) * 2;
            asm volatile("ldmatrix.sync.aligned.m8n8.x4.trans.shared.b16 {%0,%1,%2,%3}, [%4];"
                         : "=r"(b0), "=r"(b1), "=r"(b2), "=r"(b3) : "r"(baddr));
            asm volatile("mma.sync.aligned.m16n8k16.row.col.f32.f16.f16.f32 "
                         "{%0,%1,%2,%3},{%4,%5,%6,%7},{%8,%9},{%0,%1,%2,%3};"
                         : "+f"(c[2*jt][0]), "+f"(c[2*jt][1]),
                           "+f"(c[2*jt][2]), "+f"(c[2*jt][3])
                         : "r"(a0), "r"(a1), "r"(a2), "r"(a3), "r"(b0), "r"(b1));
            asm volatile("mma.sync.aligned.m16n8k16.row.col.f32.f16.f16.f32 "
                         "{%0,%1,%2,%3},{%4,%5,%6,%7},{%8,%9},{%0,%1,%2,%3};"
                         : "+f"(c[2*jt+1][0]), "+f"(c[2*jt+1][1]),
                           "+f"(c[2*jt+1][2]), "+f"(c[2*jt+1][3])
                         : "r"(a0), "r"(a1), "r"(a2), "r"(a3), "r"(b2), "r"(b3));
        }
    }

    // fragment rows
    const int r1 = row0 + wr0 + (lane >> 2);
    const int r2 = r1 + 8;

    if (EPI == 0 || EPI == 3) {
        float s1 = 1.0f, s2 = 1.0f;
        if (EPI == 0) {
            if (r1 < NND) s1 = dis[r1];
            if (r2 < NND) s2 = dis[r2];
        }
#pragma unroll
        for (int j = 0; j < NT; j++) {
            int col = j * 8 + (lane & 3) * 2;
            if (r1 < NND)
                *(__half2*)(Chalf + r1 * BN + col) =
                    __floats2half2_rn(c[j][0] * s1, c[j][1] * s1);
            if (r2 < NND)
                *(__half2*)(Chalf + r2 * BN + col) =
                    __floats2half2_rn(c[j][2] * s2, c[j][3] * s2);
        }
    } else {  // EPI 2: BN=64, NT=8, log_softmax per row
        float t[NT][4];
        float m1 = -1e30f, m2 = -1e30f;
#pragma unroll
        for (int j = 0; j < NT; j++) {
            float2 b = *(const float2*)(biasC + j * 8 + (lane & 3) * 2);
            t[j][0] = c[j][0] + b.x; t[j][1] = c[j][1] + b.y;
            t[j][2] = c[j][2] + b.x; t[j][3] = c[j][3] + b.y;
            m1 = fmaxf(m1, fmaxf(t[j][0], t[j][1]));
            m2 = fmaxf(m2, fmaxf(t[j][2], t[j][3]));
        }
#pragma unroll
        for (int o = 1; o <= 2; o <<= 1) {
            m1 = fmaxf(m1, __shfl_xor_sync(0xFFFFFFFFu, m1, o));
            m2 = fmaxf(m2, __shfl_xor_sync(0xFFFFFFFFu, m2, o));
        }
        float s1 = 0.f, s2 = 0.f;
#pragma unroll
        for (int j = 0; j < NT; j++) {
            s1 += expf(t[j][0] - m1) + expf(t[j][1] - m1);
            s2 += expf(t[j][2] - m2) + expf(t[j][3] - m2);
        }
#pragma unroll
        for (int o = 1; o <= 2; o <<= 1) {
            s1 += __shfl_xor_sync(0xFFFFFFFFu, s1, o);
            s2 += __shfl_xor_sync(0xFFFFFFFFu, s2, o);
        }
        float l1 = m1 + logf(s1);
        float l2 = m2 + logf(s2);
#pragma unroll
        for (int j = 0; j < NT; j++) {
            int col = j * 8 + (lane & 3) * 2;
            if (r1 < NND) {
                float2 r; r.x = t[j][0] - l1; r.y = t[j][1] - l1;
                *(float2*)(Cf + r1 * BN + col) = r;
            }
            if (r2 < NND) {
                float2 r; r.x = t[j][2] - l2; r.y = t[j][3] - l2;
                *(float2*)(Cf + r2 * BN + col) = r;
            }
        }
    }
}

// ---------------- CSR gather (fp16 messages) + finalize -> fp16 h ----------------
// SCALE_MSG=1: weight messages by dis[s] (layer 1); 0: pre-scaled (layer 2)
// h[v] = half(relu(dis[v]*a + bias))

template <bool SCALE_MSG>
__global__ __launch_bounds__(256)
void k_gather_fin(const __half* __restrict__ g, const float* __restrict__ dis,
                  const float* __restrict__ bias, __half* __restrict__ h)
{
    int node = (blockIdx.x * blockDim.x + threadIdx.x) >> 5;
    int lane = threadIdx.x & 31;
    if (node >= NND) return;
    int beg = row_ptr[node];
    int end = row_ptr[node + 1];
    const uint2* gp = (const uint2*)g;   // 4 halves per lane

    uint2 su = gp[node * 32 + lane];
    float2 f0 = __half22float2(*(__half2*)&su.x);
    float2 f1 = __half22float2(*(__half2*)&su.y);
    float4 a = make_float4(f0.x, f0.y, f1.x, f1.y);
    float dv = dis[node];
    if (SCALE_MSG) { a.x *= dv; a.y *= dv; a.z *= dv; a.w *= dv; }

    int e = beg;
    for (; e + 4 <= end; e += 4) {
        int s0 = __ldg(&csr_src[e + 0]);
        int s1 = __ldg(&csr_src[e + 1]);
        int s2 = __ldg(&csr_src[e + 2]);
        int s3 = __ldg(&csr_src[e + 3]);
        uint2 u0 = gp[s0 * 32 + lane];
        uint2 u1 = gp[s1 * 32 + lane];
        uint2 u2 = gp[s2 * 32 + lane];
        uint2 u3 = gp[s3 * 32 + lane];
        float2 a0 = __half22float2(*(__half2*)&u0.x), b0 = __half22float2(*(__half2*)&u0.y);
        float2 a1 = __half22float2(*(__half2*)&u1.x), b1 = __half22float2(*(__half2*)&u1.y);
        float2 a2 = __half22float2(*(__half2*)&u2.x), b2 = __half22float2(*(__half2*)&u2.y);
        float2 a3 = __half22float2(*(__half2*)&u3.x), b3 = __half22float2(*(__half2*)&u3.y);
        if (SCALE_MSG) {
            float d0 = __ldg(&dis[s0]), d1 = __ldg(&dis[s1]);
            float d2 = __ldg(&dis[s2]), d3 = __ldg(&dis[s3]);
            a.x = fmaf(a0.x, d0, a.x); a.y = fmaf(a0.y, d0, a.y);
            a.z = fmaf(b0.x, d0, a.z); a.w = fmaf(b0.y, d0, a.w);
            a.x = fmaf(a1.x, d1, a.x); a.y = fmaf(a1.y, d1, a.y);
            a.z = fmaf(b1.x, d1, a.z); a.w = fmaf(b1.y, d1, a.w);
            a.x = fmaf(a2.x, d2, a.x); a.y = fmaf(a2.y, d2, a.y);
            a.z = fmaf(b2.x, d2, a.z); a.w = fmaf(b2.y, d2, a.w);
            a.x = fmaf(a3.x, d3, a.x); a.y = fmaf(a3.y, d3, a.y);
            a.z = fmaf(b3.x, d3, a.z); a.w = fmaf(b3.y, d3, a.w);
        } else {
            a.x += a0.x + a1.x + a2.x + a3.x;
            a.y += a0.y + a1.y + a2.y + a3.y;
            a.z += b0.x + b1.x + b2.x + b3.x;
            a.w += b0.y + b1.y + b2.y + b3.y;
        }
    }
    for (; e < end; e++) {
        int s = __ldg(&csr_src[e]);
        uint2 u = gp[s * 32 + lane];
        float2 p0 = __half22float2(*(__half2*)&u.x);
        float2 p1 = __half22float2(*(__half2*)&u.y);
        if (SCALE_MSG) {
            float ds = __ldg(&dis[s]);
            a.x = fmaf(p0.x, ds, a.x); a.y = fmaf(p0.y, ds, a.y);
            a.z = fmaf(p1.x, ds, a.z); a.w = fmaf(p1.y, ds, a.w);
        } else {
            a.x += p0.x; a.y += p0.y; a.z += p1.x; a.w += p1.y;
        }
    }
    float4 b = ((const float4*)bias)[lane];
    __half2 r0 = __floats2half2_rn(fmaxf(fmaf(a.x, dv, b.x), 0.f),
                                   fmaxf(fmaf(a.y, dv, b.y), 0.f));
    __half2 r1 = __floats2half2_rn(fmaxf(fmaf(a.z, dv, b.z), 0.f),
                                   fmaxf(fmaf(a.w, dv, b.w), 0.f));
    uint2 u;
    u.x = *(uint32_t*)&r0;
    u.y = *(uint32_t*)&r1;
    ((uint2*)h)[node * 32 + lane] = u;
}

// ---------------- launch ----------------

extern "C" void kernel_launch(void* const* d_in, const int* in_sizes, int n_in,
                              void* d_out, int out_size)
{
    const float* x   = (const float*)d_in[0];
    const int*   ei  = (const int*)d_in[1];
    const int*   src = ei;
    const int*   dst = ei + NE;
    const float* W1  = (const float*)d_in[2];
    const float* b1  = (const float*)d_in[3];
    const float* W2  = (const float*)d_in[4];
    const float* b2  = (const float*)d_in[5];
    const float* Wp1 = (const float*)d_in[6];
    const float* bp1 = (const float*)d_in[7];
    const float* Wp2 = (const float*)d_in[8];
    const float* bp2 = (const float*)d_in[9];
    float* out = (float*)d_out;

    __half *g_p, *g2_p, *h_p, *w1h_p, *w2h_p, *wfh_p;
    float *dis_p, *bf_p;
    cudaGetSymbolAddress((void**)&g_p,   g_buf);
    cudaGetSymbolAddress((void**)&g2_p,  g2_buf);
    cudaGetSymbolAddress((void**)&h_p,   h_buf);
    cudaGetSymbolAddress((void**)&dis_p, dis_buf);
    cudaGetSymbolAddress((void**)&w1h_p, W1h_buf);
    cudaGetSymbolAddress((void**)&w2h_p, W2h_buf);
    cudaGetSymbolAddress((void**)&wfh_p, Wfh_buf);
    cudaGetSymbolAddress((void**)&bf_p,  bF_buf);

    // dynamic smem sizes
    const int SM_BN128 = (128 * (D + 8) + D * (128 + 8)) * 2;  // 69632
    const int SM_BN64  = (128 * (D + 8) + D * (64 + 8))  * 2;  // 53248

    static cudaStream_t s2 = nullptr;
    static cudaEvent_t ev_fork, ev_csr;
    if (!s2) {
        cudaStreamCreateWithFlags(&s2, cudaStreamNonBlocking);
        cudaEventCreateWithFlags(&ev_fork, cudaEventDisableTiming);
        cudaEventCreateWithFlags(&ev_csr,  cudaEventDisableTiming);
        cudaFuncSetAttribute((const void*)hgemm<128, false, 3>,
                             cudaFuncAttributeMaxDynamicSharedMemorySize, SM_BN128);
        cudaFuncSetAttribute((const void*)hgemm<128, true, 0>,
                             cudaFuncAttributeMaxDynamicSharedMemorySize, SM_BN128);
        cudaFuncSetAttribute((const void*)hgemm<64, true, 2>,
                             cudaFuncAttributeMaxDynamicSharedMemorySize, SM_BN64);
    }

    const int GEMM_BLOCKS   = (NND + 127) / 128;       // 782
    const int GATHER_BLOCKS = (NND * 32 + 255) / 256;  // 12500
    const int EDGE4_BLOCKS  = (NE / 4 + 255) / 256;    // 1563

    // ---- fork: CSR build + norm + weight prep on s2 ----
    cudaEventRecord(ev_fork, 0);
    cudaStreamWaitEvent(s2, ev_fork, 0);

    k_fusew<<<(D * 64 + 255) / 256, 256, 0, s2>>>(Wp1, bp1, Wp2, bp2);
    k_convW<<<(D * D + 255) / 256, 256, 0, s2>>>(W2, w2h_p, D * D);
    k_init_deg<<<(NND + 255) / 256, 256, 0, s2>>>();
    k_count_deg<<<EDGE4_BLOCKS, 256, 0, s2>>>(dst);
    k_scan1<<<SCAN_BLOCKS, SCB, 0, s2>>>();
    k_scan2<<<1, 256, 0, s2>>>();
    k_scan3<<<SCAN_BLOCKS, SCB, 0, s2>>>();
    k_fill<<<EDGE4_BLOCKS, 256, 0, s2>>>(src, dst);
    cudaEventRecord(ev_csr, s2);

    // main: convert W1, then GEMM1: g = half(x@W1)
    k_convW<<<(D * D + 255) / 256, 256>>>(W1, w1h_p, D * D);
    hgemm<128, false, 3><<<GEMM_BLOCKS, 256, SM_BN128>>>(
        x, w1h_p, nullptr, nullptr, g_p, nullptr);

    cudaStreamWaitEvent(0, ev_csr, 0);

    // ---- layer 1 aggregate: h = half(relu(dis*(dis-weighted gather g) + b1)) ----
    k_gather_fin<true><<<GATHER_BLOCKS, 256>>>(g_p, dis_p, b1, h_p);

    // ---- layer 2: g2 = half((h@W2)*dis) ; h = half(relu(dis*gather(g2) + b2)) ----
    hgemm<128, true, 0><<<GEMM_BLOCKS, 256, SM_BN128>>>(
        h_p, w2h_p, nullptr, dis_p, g2_p, nullptr);
    k_gather_fin<false><<<GATHER_BLOCKS, 256>>>(g2_p, dis_p, b2, h_p);

    // ---- fused head + log_softmax: out = logsoftmax(h @ Wf + bF) ----
    hgemm<64, true, 2><<<GEMM_BLOCKS, 256, SM_BN64>>>(
        h_p, wfh_p, bf_p, dis_p, nullptr, out);
}